// round 2
// baseline (speedup 1.0000x reference)
#include <cuda_runtime.h>
#include <math.h>

#define LL 25
#define CC 64
#define NMAX 4096
#define EMAX 32768
#define GG 45
#define EPSF 1e-6f

// degree of each SH coefficient index
__constant__ int c_deg[25] = {0,1,1,1,2,2,2,2,2,3,3,3,3,3,3,3,4,4,4,4,4,4,4,4,4};

// ---------------- scratch (static device allocations) ----------------
__device__ float g_x1[(size_t)NMAX*LL*CC];      // normalized node feats
__device__ float g_rad[(size_t)EMAX*64];        // radial weights
__device__ float g_logits[(size_t)EMAX*8];      // attention logits
__device__ float g_segmax[NMAX*8];
__device__ float g_denom[NMAX*8];
__device__ float g_agg[(size_t)NMAX*LL*128];    // aggregated messages
__device__ float g_x2[(size_t)NMAX*LL*CC];      // post-attention features
__device__ float g_gg[(size_t)NMAX*GG*128];     // grid activations (FFN)

__device__ __forceinline__ float sigmoidf_(float x){ return 1.f/(1.f+__expf(-x)); }

__device__ __forceinline__ void atomicMaxF(float* addr, float v){
    if (v >= 0.f) atomicMax((int*)addr, __float_as_int(v));
    else          atomicMin((unsigned int*)addr, __float_as_uint(v));
}

// ---------------- row-tiled small-GEMM helpers ----------------
// h rows: A = smem [25][128], W [128][64], out smem [25][64], scaled
template<int R>
__device__ __forceinline__ void mm_rows_h(const float* __restrict__ sA,
                                          const float* __restrict__ W,
                                          float* __restrict__ sOut,
                                          int base, int c, float scale){
    float acc[R];
    #pragma unroll
    for (int rr=0; rr<R; rr++) acc[rr] = 0.f;
    #pragma unroll 8
    for (int k=0; k<128; k++){
        float w = __ldg(&W[k*64+c]);
        #pragma unroll
        for (int rr=0; rr<R; rr++) acc[rr] += sA[(base+rr)*128+k]*w;
    }
    #pragma unroll
    for (int rr=0; rr<R; rr++) sOut[(base+rr)*64+c] = acc[rr]*scale;
}

// v rows: A = smem [25][64], W [64][128], out smem [25][128], scaled
template<int R>
__device__ __forceinline__ void mm_rows_v(const float* __restrict__ sA,
                                          const float* __restrict__ W,
                                          float* __restrict__ sOut,
                                          int base, int c, float scale){
    float acc[R];
    #pragma unroll
    for (int rr=0; rr<R; rr++) acc[rr] = 0.f;
    #pragma unroll 8
    for (int k=0; k<64; k++){
        float w = __ldg(&W[k*128+c]);
        #pragma unroll
        for (int rr=0; rr<R; rr++) acc[rr] += sA[(base+rr)*64+k]*w;
    }
    #pragma unroll
    for (int rr=0; rr<R; rr++) sOut[(base+rr)*128+c] = acc[rr]*scale;
}

// out rows: A = smem [25][128], W [128][64], out global [25][64] + residual
template<int R>
__device__ __forceinline__ void mm_rows_out64(const float* __restrict__ sA,
                                              const float* __restrict__ W,
                                              const float* __restrict__ res,
                                              float* __restrict__ outp,
                                              int base, int c){
    float acc[R];
    #pragma unroll
    for (int rr=0; rr<R; rr++) acc[rr] = 0.f;
    #pragma unroll 8
    for (int k=0; k<128; k++){
        float w = __ldg(&W[k*64+c]);
        #pragma unroll
        for (int rr=0; rr<R; rr++) acc[rr] += sA[(base+rr)*128+k]*w;
    }
    #pragma unroll
    for (int rr=0; rr<R; rr++)
        outp[(base+rr)*64+c] = acc[rr] + res[(base+rr)*64+c];
}

// ff1 rows: A = smem [25][64], W [64][128], out smem [25][128]
template<int R>
__device__ __forceinline__ void mm_rows_ff1(const float* __restrict__ sA,
                                            const float* __restrict__ W,
                                            float* __restrict__ sOut,
                                            int base, int f){
    float acc[R];
    #pragma unroll
    for (int rr=0; rr<R; rr++) acc[rr] = 0.f;
    #pragma unroll 8
    for (int k=0; k<64; k++){
        float w = __ldg(&W[k*128+f]);
        #pragma unroll
        for (int rr=0; rr<R; rr++) acc[rr] += sA[(base+rr)*64+k]*w;
    }
    #pragma unroll
    for (int rr=0; rr<R; rr++) sOut[(base+rr)*128+f] = acc[rr];
}

// ---------------- kernels ----------------

__global__ void k_init(int N){
    int i = blockIdx.x*blockDim.x + threadIdx.x;
    int stride = gridDim.x*blockDim.x;
    int tot = N*LL*128;
    for (int idx=i; idx<tot; idx+=stride) g_agg[idx] = 0.f;
    if (i < N*8){ g_denom[i] = 0.f; g_segmax[i] = -1e30f; }
}

// RMS norm per (node, degree) over (m, channel); affine per (degree, channel)
__global__ void k_norm1(const float* __restrict__ nf, const float* __restrict__ w, int N){
    int n = blockIdx.x; int t = threadIdx.x;
    __shared__ float ssq[5], sinv[5];
    if (t < 5) ssq[t] = 0.f;
    __syncthreads();
    const float* src = nf + (size_t)n*1600;
    #pragma unroll
    for (int d=0; d<5; d++){
        int b = d*d*64, cnt = (2*d+1)*64;
        float a = 0.f;
        for (int idx=t; idx<cnt; idx+=128){ float v = src[b+idx]; a += v*v; }
        // warp-level pre-reduction to cut shared atomics
        #pragma unroll
        for (int off=16; off>0; off>>=1) a += __shfl_down_sync(0xffffffffu, a, off);
        if ((t & 31) == 0) atomicAdd(&ssq[d], a);
    }
    __syncthreads();
    if (t < 5) sinv[t] = rsqrtf(ssq[t] / ((2.f*t+1.f)*64.f) + EPSF);
    __syncthreads();
    float* dst = g_x1 + (size_t)n*1600;
    for (int idx=t; idx<1600; idx+=128){
        int l = idx>>6, c = idx&63;
        int d = c_deg[l];
        dst[idx] = src[idx] * sinv[d] * __ldg(&w[d*64+c]);
    }
}

// per-edge: radial MLP + row-0 rotation + gated h0 + attention logits
__global__ __launch_bounds__(128)
void k_edge_logits(const float* __restrict__ dist, const int* __restrict__ species,
                   const int* __restrict__ senders, const int* __restrict__ receivers,
                   const float* __restrict__ wigner,
                   const float* __restrict__ W_edge, const float* __restrict__ emb_src,
                   const float* __restrict__ emb_dst,
                   const float* __restrict__ W_r1, const float* __restrict__ b_r1,
                   const float* __restrict__ W_r2, const float* __restrict__ b_r2,
                   const float* __restrict__ W_msg, const float* __restrict__ W_alpha,
                   const float* __restrict__ alpha_vec, int E){
    int e = blockIdx.x; int t = threadIdx.x;
    __shared__ float sdist[64], se[64], sr1[64], srad[64], sm0[128], sh0[64];
    int s = senders[e], r = receivers[e];
    int sps = species[s], spr = species[r];
    if (t < 64) sdist[t] = dist[(size_t)e*64+t];
    __syncthreads();
    if (t < 64){
        float acc = __ldg(&emb_src[sps*64+t]) + __ldg(&emb_dst[spr*64+t]);
        #pragma unroll 8
        for (int k=0; k<64; k++) acc += sdist[k]*__ldg(&W_edge[k*64+t]);
        se[t] = acc;
    }
    __syncthreads();
    if (t < 64){
        float acc = __ldg(&b_r1[t]);
        #pragma unroll 8
        for (int k=0; k<64; k++) acc += se[k]*__ldg(&W_r1[k*64+t]);
        sr1[t] = acc * sigmoidf_(acc);  // silu
    }
    __syncthreads();
    if (t < 64){
        float acc = __ldg(&b_r2[t]);
        #pragma unroll 8
        for (int k=0; k<64; k++) acc += sr1[k]*__ldg(&W_r2[k*64+t]);
        srad[t] = acc;
        g_rad[(size_t)e*64+t] = acc;
    }
    __syncthreads();
    // row-0 of rotated message: m0[c] = sum_j wig[0][j]*msg[j][c]
    {
        const float* wg = wigner + (size_t)e*625;
        const float* xb = (t < 64) ? (g_x1 + (size_t)s*1600 + t)
                                   : (g_x1 + (size_t)r*1600 + (t-64));
        float acc = 0.f;
        #pragma unroll
        for (int j=0; j<LL; j++) acc += __ldg(&wg[j]) * xb[j*64];
        sm0[t] = acc;
    }
    __syncthreads();
    if (t < 64){
        float acc = 0.f;
        #pragma unroll 8
        for (int k=0; k<128; k++) acc += sm0[k]*__ldg(&W_msg[k*64+t]); // degree-0 slice
        acc *= srad[t];
        sh0[t] = acc * sigmoidf_(acc);   // gated h0
    }
    __syncthreads();
    {
        float acc = 0.f;
        #pragma unroll 8
        for (int k=0; k<64; k++) acc += sh0[k]*__ldg(&W_alpha[k*128+t]);
        float a = (acc > 0.f) ? acc : 0.2f*acc;   // leaky relu 0.2
        float prod = a * __ldg(&alpha_vec[t]);    // t == head*16+ai
        #pragma unroll
        for (int off=8; off>0; off>>=1) prod += __shfl_down_sync(0xffffffffu, prod, off);
        if ((t & 15) == 0) g_logits[(size_t)e*8 + (t>>4)] = prod;
    }
}

__global__ void k_segmax(const int* __restrict__ receivers, int E){
    int i = blockIdx.x*blockDim.x + threadIdx.x;
    if (i >= E*8) return;
    int e = i>>3, hh = i&7;
    atomicMaxF(&g_segmax[receivers[e]*8+hh], g_logits[i]);
}

__global__ void k_denom(const int* __restrict__ receivers, int E){
    int i = blockIdx.x*blockDim.x + threadIdx.x;
    if (i >= E*8) return;
    int e = i>>3, hh = i&7;
    int r = receivers[e];
    atomicAdd(&g_denom[r*8+hh], __expf(g_logits[i] - g_segmax[r*8+hh]));
}

// main edge kernel: gather -> rotate -> W_msg*rad*gate -> W_val*attn -> rotate back -> atomic agg
__global__ __launch_bounds__(128)
void k_edge_main(const int* __restrict__ senders, const int* __restrict__ receivers,
                 const float* __restrict__ wigner,
                 const float* __restrict__ W_msg, const float* __restrict__ W_val, int E){
    int e = blockIdx.x; int t = threadIdx.x;
    __shared__ float swig[625];
    __shared__ float smrot[LL*128];
    __shared__ float sh[LL*64];
    __shared__ float sv[LL*128];
    __shared__ float srad[64], ssig[64], sattn[8];

    int s = senders[e], r = receivers[e];
    for (int i=t; i<625; i+=128) swig[i] = wigner[(size_t)e*625+i];
    if (t < 64) srad[t] = g_rad[(size_t)e*64+t];
    if (t < 8){
        float lg = g_logits[(size_t)e*8+t];
        sattn[t] = __expf(lg - g_segmax[r*8+t]) / (g_denom[r*8+t] + EPSF);
    }
    __syncthreads();

    // gather my column of concat(x[s], x[r]) and rotate: msgrot[i][t] = sum_j wig[i][j]*mc[j]
    float mc[LL];
    {
        const float* xb = (t < 64) ? (g_x1 + (size_t)s*1600 + t)
                                   : (g_x1 + (size_t)r*1600 + (t-64));
        #pragma unroll
        for (int j=0; j<LL; j++) mc[j] = xb[j*64];
    }
    #pragma unroll 1
    for (int i=0; i<LL; i++){
        float acc = 0.f;
        #pragma unroll
        for (int j=0; j<LL; j++) acc += swig[i*25+j]*mc[j];
        smrot[i*128+t] = acc;
    }
    __syncthreads();

    // h0 (degree 0) + gate
    if (t < 64){
        float acc = 0.f;
        #pragma unroll 8
        for (int k=0; k<128; k++) acc += smrot[k]*__ldg(&W_msg[k*64+t]);
        acc *= srad[t];
        float sg = sigmoidf_(acc);
        ssig[t] = sg;
        sh[t] = acc*sg;
    }
    __syncthreads();

    // remaining degrees, split across the two half-blocks (12 rows each)
    {
        int c = t & 63;
        float scale = srad[c]*ssig[c];
        if (t < 64){
            mm_rows_h<3>(smrot, W_msg + 1*8192, sh, 1,  c, scale);  // degree 1
            mm_rows_h<9>(smrot, W_msg + 4*8192, sh, 16, c, scale);  // degree 4
        } else {
            mm_rows_h<5>(smrot, W_msg + 2*8192, sh, 4,  c, scale);  // degree 2
            mm_rows_h<7>(smrot, W_msg + 3*8192, sh, 9,  c, scale);  // degree 3
        }
    }
    __syncthreads();

    // v = h @ W_val[deg], scaled by per-head attention
    {
        float attn = sattn[t>>4];
        mm_rows_v<1>(sh, W_val + 0*8192, sv, 0,  t, attn);
        mm_rows_v<3>(sh, W_val + 1*8192, sv, 1,  t, attn);
        mm_rows_v<5>(sh, W_val + 2*8192, sv, 4,  t, attn);
        mm_rows_v<7>(sh, W_val + 3*8192, sv, 9,  t, attn);
        mm_rows_v<9>(sh, W_val + 4*8192, sv, 16, t, attn);
    }
    __syncthreads();

    // rotate back with wigner^T and scatter-add to receiver
    float* aggb = g_agg + ((size_t)r*LL)*128 + t;
    #pragma unroll 1
    for (int i=0; i<LL; i++){
        float acc = 0.f;
        #pragma unroll
        for (int j=0; j<LL; j++) acc += swig[j*25+i]*sv[j*128+t];
        atomicAdd(aggb + i*128, acc);
    }
}

// x2 = agg @ W_out[deg] + node_feats
__global__ __launch_bounds__(128)
void k_wout(const float* __restrict__ nf, const float* __restrict__ W_out, int N){
    int n = blockIdx.x; int t = threadIdx.x;
    __shared__ float sagg[LL*128];
    for (int i=t; i<LL*128; i+=128) sagg[i] = g_agg[(size_t)n*LL*128 + i];
    __syncthreads();
    int c = t & 63;
    const float* res = nf + (size_t)n*1600;
    float* outp = g_x2 + (size_t)n*1600;
    if (t < 64){
        mm_rows_out64<1>(sagg, W_out + 0*8192, res, outp, 0,  c);
        mm_rows_out64<3>(sagg, W_out + 1*8192, res, outp, 1,  c);
        mm_rows_out64<9>(sagg, W_out + 4*8192, res, outp, 16, c);
    } else {
        mm_rows_out64<5>(sagg, W_out + 2*8192, res, outp, 4,  c);
        mm_rows_out64<7>(sagg, W_out + 3*8192, res, outp, 9,  c);
    }
}

// FFN part A: norm2 -> ff1 -> to_grid -> W_grid+silu -> g_gg
__global__ __launch_bounds__(128)
void k_ffn_a(const float* __restrict__ norm2w, const float* __restrict__ W_ff1,
             const float* __restrict__ to_grid, const float* __restrict__ W_grid,
             const float* __restrict__ b_grid, int N){
    int n = blockIdx.x; int t = threadIdx.x;
    __shared__ float sx[LL*64];      // normalized input
    __shared__ float st1[LL*128];    // ff1 output
    __shared__ float sg[GG*128];     // grid
    __shared__ float stg[GG*LL];     // to_grid weights
    __shared__ float ssq[5], sinv[5];

    if (t < 5) ssq[t] = 0.f;
    for (int i=t; i<GG*LL; i+=128) stg[i] = __ldg(&to_grid[i]);
    __syncthreads();

    const float* xb = g_x2 + (size_t)n*1600;
    #pragma unroll
    for (int d=0; d<5; d++){
        int b = d*d*64, cnt = (2*d+1)*64;
        float a = 0.f;
        for (int idx=t; idx<cnt; idx+=128){ float v = xb[b+idx]; sx[b+idx] = v; a += v*v; }
        #pragma unroll
        for (int off=16; off>0; off>>=1) a += __shfl_down_sync(0xffffffffu, a, off);
        if ((t & 31) == 0) atomicAdd(&ssq[d], a);
    }
    __syncthreads();
    if (t < 5) sinv[t] = rsqrtf(ssq[t] / ((2.f*t+1.f)*64.f) + EPSF);
    __syncthreads();
    for (int idx=t; idx<1600; idx+=128){
        int l = idx>>6, c = idx&63;
        int d = c_deg[l];
        sx[idx] *= sinv[d] * __ldg(&norm2w[d*64+c]);
    }
    __syncthreads();

    // ff1: [25,64] -> [25,128]
    mm_rows_ff1<1>(sx, W_ff1 + 0*8192, st1, 0,  t);
    mm_rows_ff1<3>(sx, W_ff1 + 1*8192, st1, 1,  t);
    mm_rows_ff1<5>(sx, W_ff1 + 2*8192, st1, 4,  t);
    mm_rows_ff1<7>(sx, W_ff1 + 3*8192, st1, 9,  t);
    mm_rows_ff1<9>(sx, W_ff1 + 4*8192, st1, 16, t);
    __syncthreads();

    // to_grid: g[p][t] = sum_l tg[p][l] * t1[l][t]
    #pragma unroll 1
    for (int p=0; p<GG; p++){
        float acc = 0.f;
        #pragma unroll
        for (int l=0; l<LL; l++) acc += stg[p*25+l]*st1[l*128+t];
        sg[p*128+t] = acc;
    }
    __syncthreads();

    // W_grid + silu, 5-row tiles (45 = 9*5)
    float bg = __ldg(&b_grid[t]);
    #pragma unroll 1
    for (int pt=0; pt<9; pt++){
        float acc[5] = {0.f,0.f,0.f,0.f,0.f};
        #pragma unroll 4
        for (int k=0; k<128; k++){
            float w = __ldg(&W_grid[k*128+t]);
            #pragma unroll
            for (int rr=0; rr<5; rr++) acc[rr] += sg[(pt*5+rr)*128+k]*w;
        }
        #pragma unroll
        for (int rr=0; rr<5; rr++){
            float z = acc[rr] + bg;
            g_gg[((size_t)n*GG + pt*5+rr)*128 + t] = z * sigmoidf_(z);
        }
    }
}

// FFN part B: from_grid -> ff2 + residual -> out
__global__ __launch_bounds__(128)
void k_ffn_b(const float* __restrict__ from_grid, const float* __restrict__ W_ff2,
             float* __restrict__ out, int N){
    int n = blockIdx.x; int t = threadIdx.x;
    __shared__ float sgg[GG*128];
    __shared__ float sfg[LL*GG];
    __shared__ float sy2[LL*128];

    for (int i=t; i<GG*128; i+=128) sgg[i] = g_gg[(size_t)n*GG*128 + i];
    for (int i=t; i<LL*GG; i+=128) sfg[i] = __ldg(&from_grid[i]);
    __syncthreads();

    #pragma unroll 1
    for (int l=0; l<LL; l++){
        float acc = 0.f;
        #pragma unroll
        for (int p=0; p<GG; p++) acc += sfg[l*45+p]*sgg[p*128+t];
        sy2[l*128+t] = acc;
    }
    __syncthreads();

    int c = t & 63;
    const float* res = g_x2 + (size_t)n*1600;
    float* outp = out + (size_t)n*1600;
    if (t < 64){
        mm_rows_out64<1>(sy2, W_ff2 + 0*8192, res, outp, 0,  c);
        mm_rows_out64<3>(sy2, W_ff2 + 1*8192, res, outp, 1,  c);
        mm_rows_out64<9>(sy2, W_ff2 + 4*8192, res, outp, 16, c);
    } else {
        mm_rows_out64<5>(sy2, W_ff2 + 2*8192, res, outp, 4,  c);
        mm_rows_out64<7>(sy2, W_ff2 + 3*8192, res, outp, 9,  c);
    }
}

// ---------------- host launcher ----------------
extern "C" void kernel_launch(void* const* d_in, const int* in_sizes, int n_in,
                              void* d_out, int out_size){
    // Auto-detect whether the scalar 'n_node' input is materialized at index 6.
    // If present, in_sizes[6] is tiny (1); if dropped, index 6 is norm1_w (320 elems).
    int p = (in_sizes[6] <= 4) ? 7 : 6;

    const float* node_feats = (const float*)d_in[0];
    const int*   species    = (const int*)  d_in[1];
    const float* edge_dist  = (const float*)d_in[2];
    const int*   senders    = (const int*)  d_in[3];
    const int*   receivers  = (const int*)  d_in[4];
    const float* wigner     = (const float*)d_in[5];
    const float* norm1_w    = (const float*)d_in[p+0];
    const float* norm2_w    = (const float*)d_in[p+1];
    const float* W_edge     = (const float*)d_in[p+2];
    const float* emb_src    = (const float*)d_in[p+3];
    const float* emb_dst    = (const float*)d_in[p+4];
    const float* W_r1       = (const float*)d_in[p+5];
    const float* b_r1       = (const float*)d_in[p+6];
    const float* W_r2       = (const float*)d_in[p+7];
    const float* b_r2       = (const float*)d_in[p+8];
    const float* W_msg      = (const float*)d_in[p+9];
    const float* W_alpha    = (const float*)d_in[p+10];
    const float* alpha_vec  = (const float*)d_in[p+11];
    const float* W_val      = (const float*)d_in[p+12];
    const float* W_out      = (const float*)d_in[p+13];
    const float* W_ff1      = (const float*)d_in[p+14];
    const float* to_grid    = (const float*)d_in[p+15];
    const float* from_grid  = (const float*)d_in[p+16];
    const float* W_grid     = (const float*)d_in[p+17];
    const float* b_grid     = (const float*)d_in[p+18];
    const float* W_ff2      = (const float*)d_in[p+19];

    int N = in_sizes[0] / (LL*CC);
    int E = in_sizes[3];
    if (N > NMAX) N = NMAX;
    if (E > EMAX) E = EMAX;

    k_init<<<2048, 256>>>(N);
    k_norm1<<<N, 128>>>(node_feats, norm1_w, N);
    k_edge_logits<<<E, 128>>>(edge_dist, species, senders, receivers, wigner,
                              W_edge, emb_src, emb_dst, W_r1, b_r1, W_r2, b_r2,
                              W_msg, W_alpha, alpha_vec, E);
    int segthreads = 256;
    int segblocks = (E*8 + segthreads - 1) / segthreads;
    k_segmax<<<segblocks, segthreads>>>(receivers, E);
    k_denom<<<segblocks, segthreads>>>(receivers, E);
    k_edge_main<<<E, 128>>>(senders, receivers, wigner, W_msg, W_val, E);
    k_wout<<<N, 128>>>(node_feats, W_out, N);
    k_ffn_a<<<N, 128>>>(norm2_w, W_ff1, to_grid, W_grid, b_grid, N);
    k_ffn_b<<<N, 128>>>(from_grid, W_ff2, (float*)d_out, N);
}